// round 6
// baseline (speedup 1.0000x reference)
#include <cuda_runtime.h>
#include <cuda_bf16.h>
#include <cstddef>
#include <cstdint>

// ---------------------------------------------------------------------------
// HyperNodeAggregation via mma.sync bf16 (compute_103-safe; no tcgen05).
// B=4, C=512, N=HW=4096, nd=4096.
//
// All-NT restructure (per batch b; X = x[b] reshaped [C, N], K-major):
//   s   = X·1 ;  u = Wq s ;  w2 = Wk s + N·bk
//   G   = X Xᵀ                                   [C, C]   (symmetric)
//   M1  = Wq Gᵀ(=G)                              [ND, C]
//   E   = M1 Wkᵀ + u bkᵀ + bq w2ᵀ               [ND, ND]
//   A   = softmax_rows(E)
//   PT  = A Xᵀ                                   [ND, C]
//   out = Wv PTᵀ + bv        (Σk A = 1 folds bv)           [C, ND]
//
// Every GEMM is D = A·Bᵀ, both operands K-major -> mma.sync row.col NT.
// fp32 operands split hi/lo bf16; 3 passes (hh+hl+lh), fp32 accumulate.
// ---------------------------------------------------------------------------

#define CB   4
#define CC   512
#define ND   4096
#define NSP  4096

// ---------------- scratch (static device memory; no allocs) ----------------
__device__ float g_s  [CB * CC];
__device__ float g_u  [CB * ND];
__device__ float g_w2 [CB * ND];
__device__ float g_G  [CB * CC * CC];
__device__ float g_M1 [(size_t)CB * ND * CC];
__device__ float g_PT [(size_t)CB * ND * CC];
__device__ float g_E  [(size_t)CB * ND * ND];          // 268 MB

__device__ __nv_bfloat16 g_xh [(size_t)CB * CC * NSP];
__device__ __nv_bfloat16 g_xl [(size_t)CB * CC * NSP];
__device__ __nv_bfloat16 g_wqh[(size_t)ND * CC];
__device__ __nv_bfloat16 g_wql[(size_t)ND * CC];
__device__ __nv_bfloat16 g_wkh[(size_t)ND * CC];
__device__ __nv_bfloat16 g_wkl[(size_t)ND * CC];
__device__ __nv_bfloat16 g_wvh[(size_t)CC * CC];
__device__ __nv_bfloat16 g_wvl[(size_t)CC * CC];
__device__ __nv_bfloat16 g_gh [(size_t)CB * CC * CC];
__device__ __nv_bfloat16 g_gl [(size_t)CB * CC * CC];
__device__ __nv_bfloat16 g_m1h[(size_t)CB * ND * CC];
__device__ __nv_bfloat16 g_m1l[(size_t)CB * ND * CC];
__device__ __nv_bfloat16 g_pth[(size_t)CB * ND * CC];
__device__ __nv_bfloat16 g_ptl[(size_t)CB * ND * CC];
__device__ __nv_bfloat16 g_ah [(size_t)CB * ND * ND];  // 134 MB
__device__ __nv_bfloat16 g_al [(size_t)CB * ND * ND];  // 134 MB

// ---------------- PTX helpers (compute_103-safe only) -----------------------
__device__ __forceinline__ uint32_t smem_u32(const void* p) {
    uint32_t a;
    asm("{ .reg .u64 t; cvta.to.shared.u64 t, %1; cvt.u32.u64 %0, t; }"
        : "=r"(a) : "l"(p));
    return a;
}

#define LDSM_X4(r, addr)                                                       \
    asm volatile("ldmatrix.sync.aligned.m8n8.x4.shared.b16 {%0,%1,%2,%3}, [%4];" \
                 : "=r"((r)[0]), "=r"((r)[1]), "=r"((r)[2]), "=r"((r)[3])      \
                 : "r"(addr))

#define MMA16816(d, a, b0, b1)                                                 \
    asm volatile("mma.sync.aligned.m16n8k16.row.col.f32.bf16.bf16.f32 "        \
                 "{%0,%1,%2,%3}, {%4,%5,%6,%7}, {%8,%9}, {%0,%1,%2,%3};"       \
                 : "+f"((d)[0]), "+f"((d)[1]), "+f"((d)[2]), "+f"((d)[3])      \
                 : "r"((a)[0]), "r"((a)[1]), "r"((a)[2]), "r"((a)[3]),         \
                   "r"(b0), "r"(b1))

// ---------------- dynamic smem layout: 4 tiles of 128 rows x 64 bf16 --------
#define SM_AH 0
#define SM_AL 16384
#define SM_BH 32768
#define SM_BL 49152
#define MM_SMEM 65536

// ---------------------------------------------------------------------------
// mma_nt_gemm: C[m,n] = sum_k A[m,k]*B[n,k], fp32 out; A/B hi/lo bf16 K-major
// (lda = ldb = K). Grid: (N/128, M/128, batch), 256 threads (8 warps).
// Warp tile 64(M) x 32(N): 4 m-frags (m16) x 4 n-frags (n8), k16 steps.
// EPI: 0 none; 1 +em1[m]; 2 +em1[m]*en1[n] + em2[m]*en2[n]
// ---------------------------------------------------------------------------
template <int EPI>
__global__ __launch_bounds__(256)
void mma_nt_gemm(const __nv_bfloat16* __restrict__ Ah, const __nv_bfloat16* __restrict__ Al,
                 const __nv_bfloat16* __restrict__ Bh, const __nv_bfloat16* __restrict__ Bl,
                 float* __restrict__ Cm, int K, int ldc,
                 size_t sA, size_t sB, size_t sC,
                 const float* __restrict__ em1, int sm1,
                 const float* __restrict__ en1, int sn1,
                 const float* __restrict__ em2, int sm2,
                 const float* __restrict__ en2, int sn2)
{
    extern __shared__ __align__(128) char smem[];
    const uint32_t sb = smem_u32(smem);
    const int tid  = threadIdx.x;
    const int wid  = tid >> 5;
    const int lane = tid & 31;
    const int b    = blockIdx.z;
    const int n0   = blockIdx.x * 128;
    const int m0   = blockIdx.y * 128;
    const int wm   = wid & 1;        // 2 warps along M
    const int wn   = wid >> 1;       // 4 warps along N

    const __nv_bfloat16* Aph = Ah + (size_t)b * sA + (size_t)m0 * K;
    const __nv_bfloat16* Apl = Al + (size_t)b * sA + (size_t)m0 * K;
    const __nv_bfloat16* Bph = Bh + (size_t)b * sB + (size_t)n0 * K;
    const __nv_bfloat16* Bpl = Bl + (size_t)b * sB + (size_t)n0 * K;
    float* Cp = Cm + (size_t)b * sC;

    // ldmatrix lane decomposition
    const int sub = lane >> 3, r8 = lane & 7;
    // A x4 blocks: sub0: m+0-7 @klo | sub1: m+8-15 @klo | sub2: m0-7 @khi | sub3: m8-15 @khi
    const int arow  = wm * 64 + (sub & 1) * 8 + r8;   // + mf*16
    const int acsub = sub >> 1;
    // B x4 blocks: sub0: n+0-7 @klo | sub1: n+0-7 @khi | sub2: n+8-15 @klo | sub3: n+8-15 @khi
    const int brow  = wn * 32 + (sub >> 1) * 8 + r8;  // + nf2*16
    const int bcsub = sub & 1;

    float acc[4][4][4];
#pragma unroll
    for (int i = 0; i < 4; i++)
#pragma unroll
        for (int j = 0; j < 4; j++)
#pragma unroll
            for (int k = 0; k < 4; k++) acc[i][j][k] = 0.f;

    const int nchunks = K >> 6;
    for (int ch = 0; ch < nchunks; ch++) {
        const int kb = ch * 64;
        // ---- stage A/B hi+lo tiles: 128 rows x 64 bf16, swizzled 16B chunks
        for (int f = tid; f < 1024; f += 256) {
            const int row = f >> 3, sg = f & 7;
            const uint32_t so = (uint32_t)(row * 128) + (uint32_t)((sg ^ (row & 7)) << 4);
            *(uint4*)(smem + SM_AH + so) = *((const uint4*)(Aph + (size_t)row * K + kb) + sg);
            *(uint4*)(smem + SM_AL + so) = *((const uint4*)(Apl + (size_t)row * K + kb) + sg);
            *(uint4*)(smem + SM_BH + so) = *((const uint4*)(Bph + (size_t)row * K + kb) + sg);
            *(uint4*)(smem + SM_BL + so) = *((const uint4*)(Bpl + (size_t)row * K + kb) + sg);
        }
        __syncthreads();

#pragma unroll
        for (int pass = 0; pass < 3; pass++) {      // hh, hl, lh
            const uint32_t abase = sb + ((pass == 2) ? SM_AL : SM_AH);
            const uint32_t bbase = sb + ((pass == 1) ? SM_BL : SM_BH);
#pragma unroll
            for (int ks = 0; ks < 4; ks++) {        // 4 x k16 within the 64-chunk
                uint32_t aR[4][4];
#pragma unroll
                for (int mf = 0; mf < 4; mf++) {
                    const int row = arow + mf * 16;
                    const uint32_t ad = abase + (uint32_t)(row * 128)
                                      + (uint32_t)((((2 * ks + acsub) ^ (row & 7)) << 4));
                    LDSM_X4(aR[mf], ad);
                }
                uint32_t bR[2][4];
#pragma unroll
                for (int nf2 = 0; nf2 < 2; nf2++) {
                    const int row = brow + nf2 * 16;
                    const uint32_t bd = bbase + (uint32_t)(row * 128)
                                      + (uint32_t)((((2 * ks + bcsub) ^ (row & 7)) << 4));
                    LDSM_X4(bR[nf2], bd);
                }
#pragma unroll
                for (int mf = 0; mf < 4; mf++)
#pragma unroll
                    for (int nf = 0; nf < 4; nf++)
                        MMA16816(acc[mf][nf], aR[mf],
                                 bR[nf >> 1][(nf & 1) * 2 + 0],
                                 bR[nf >> 1][(nf & 1) * 2 + 1]);
            }
        }
        __syncthreads();
    }

    // ---- epilogue: c0,c1 at (m=g, n=2t..2t+1); c2,c3 at (m=g+8, same n)
    const int g = lane >> 2, t = lane & 3;
#pragma unroll
    for (int mf = 0; mf < 4; mf++) {
        const int mA = m0 + wm * 64 + mf * 16 + g;
        const int mB = mA + 8;
        float e1A = 0.f, e2A = 0.f, e1B = 0.f, e2B = 0.f;
        if (EPI == 1) {
            e1A = __ldg(em1 + (size_t)b * sm1 + mA);
            e1B = __ldg(em1 + (size_t)b * sm1 + mB);
        }
        if (EPI == 2) {
            e1A = __ldg(em1 + (size_t)b * sm1 + mA);
            e2A = __ldg(em2 + (size_t)b * sm2 + mA);
            e1B = __ldg(em1 + (size_t)b * sm1 + mB);
            e2B = __ldg(em2 + (size_t)b * sm2 + mB);
        }
#pragma unroll
        for (int nf = 0; nf < 4; nf++) {
            const int n = n0 + wn * 32 + nf * 8 + t * 2;
            float2 vA, vB;
            vA.x = acc[mf][nf][0]; vA.y = acc[mf][nf][1];
            vB.x = acc[mf][nf][2]; vB.y = acc[mf][nf][3];
            if (EPI == 1) { vA.x += e1A; vA.y += e1A; vB.x += e1B; vB.y += e1B; }
            if (EPI == 2) {
                const float n1a = __ldg(en1 + (size_t)b * sn1 + n);
                const float n1b = __ldg(en1 + (size_t)b * sn1 + n + 1);
                const float n2a = __ldg(en2 + (size_t)b * sn2 + n);
                const float n2b = __ldg(en2 + (size_t)b * sn2 + n + 1);
                vA.x += e1A * n1a + e2A * n2a;  vA.y += e1A * n1b + e2A * n2b;
                vB.x += e1B * n1a + e2B * n2a;  vB.y += e1B * n1b + e2B * n2b;
            }
            *(float2*)(Cp + (size_t)mA * ldc + n) = vA;
            *(float2*)(Cp + (size_t)mB * ldc + n) = vB;
        }
    }
}

// ---------------------------------------------------------------------------
// hi/lo split: h = bf16(x), l = bf16(x - h). 4 floats/thread.
// ---------------------------------------------------------------------------
__global__ __launch_bounds__(256) void split_k(const float* __restrict__ src,
                                               __nv_bfloat16* __restrict__ h,
                                               __nv_bfloat16* __restrict__ l) {
    const size_t i = (size_t)blockIdx.x * 256 + threadIdx.x;
    const float4 v = ((const float4*)src)[i];
    __nv_bfloat16 hx = __float2bfloat16(v.x);
    __nv_bfloat16 hy = __float2bfloat16(v.y);
    __nv_bfloat16 hz = __float2bfloat16(v.z);
    __nv_bfloat16 hw = __float2bfloat16(v.w);
    __nv_bfloat162 h01; h01.x = hx; h01.y = hy;
    __nv_bfloat162 h23; h23.x = hz; h23.y = hw;
    ((__nv_bfloat162*)h)[2 * i + 0] = h01;
    ((__nv_bfloat162*)h)[2 * i + 1] = h23;
    __nv_bfloat162 l01, l23;
    l01.x = __float2bfloat16(v.x - __bfloat162float(hx));
    l01.y = __float2bfloat16(v.y - __bfloat162float(hy));
    l23.x = __float2bfloat16(v.z - __bfloat162float(hz));
    l23.y = __float2bfloat16(v.w - __bfloat162float(hw));
    ((__nv_bfloat162*)l)[2 * i + 0] = l01;
    ((__nv_bfloat162*)l)[2 * i + 1] = l23;
}

// ---------------------------------------------------------------------------
__global__ __launch_bounds__(128) void rowsum_k(const float* __restrict__ x,
                                                float* __restrict__ s) {
    const int rc = blockIdx.x;
    const float4* p4 = (const float4*)(x + (size_t)rc * NSP);
    const int tid = threadIdx.x;
    float a = 0.f;
    for (int i = tid; i < NSP / 4; i += 128) {
        float4 v = p4[i];
        a += (v.x + v.y) + (v.z + v.w);
    }
#pragma unroll
    for (int o = 16; o > 0; o >>= 1) a += __shfl_xor_sync(0xffffffffu, a, o);
    __shared__ float red[4];
    if ((tid & 31) == 0) red[tid >> 5] = a;
    __syncthreads();
    if (tid == 0) s[rc] = (red[0] + red[1]) + (red[2] + red[3]);
}

// ---------------------------------------------------------------------------
__global__ __launch_bounds__(128) void uw_k(const float* __restrict__ Wq,
                                            const float* __restrict__ Wk,
                                            const float* __restrict__ bk,
                                            const float* __restrict__ s,
                                            float* __restrict__ u,
                                            float* __restrict__ w2) {
    __shared__ float ss[CB * CC];
    const int tid = threadIdx.x;
    for (int i = tid; i < CB * CC; i += 128) ss[i] = s[i];
    __syncthreads();
    const int q = blockIdx.x * 128 + tid;
    float au[CB] = {0.f, 0.f, 0.f, 0.f};
    float aw[CB] = {0.f, 0.f, 0.f, 0.f};
    const float* wqr = Wq + (size_t)q * CC;
    const float* wkr = Wk + (size_t)q * CC;
    for (int c = 0; c < CC; c++) {
        const float wq = wqr[c], wk = wkr[c];
#pragma unroll
        for (int bb = 0; bb < CB; bb++) {
            const float sv = ss[bb * CC + c];
            au[bb] += wq * sv;
            aw[bb] += wk * sv;
        }
    }
    const float bkv = bk[q];
#pragma unroll
    for (int bb = 0; bb < CB; bb++) {
        u[bb * ND + q]  = au[bb];
        w2[bb * ND + q] = aw[bb] + (float)NSP * bkv;
    }
}

// ---------------------------------------------------------------------------
// Row softmax over E (fp32), writing attn directly as hi/lo bf16.
// ---------------------------------------------------------------------------
__global__ __launch_bounds__(256) void softmax_bf(const float* __restrict__ E,
                                                  __nv_bfloat16* __restrict__ ah,
                                                  __nv_bfloat16* __restrict__ al) {
    const size_t row = blockIdx.x;
    const float* p = E + row * (size_t)ND;
    const int tid = threadIdx.x;
    float v[16];
    float mx = -3.4e38f;
#pragma unroll
    for (int i = 0; i < 16; i++) {
        v[i] = p[tid + i * 256];
        mx = fmaxf(mx, v[i]);
    }
#pragma unroll
    for (int o = 16; o > 0; o >>= 1)
        mx = fmaxf(mx, __shfl_xor_sync(0xffffffffu, mx, o));
    __shared__ float redm[8];
    __shared__ float reds[8];
    if ((tid & 31) == 0) redm[tid >> 5] = mx;
    __syncthreads();
    mx = fmaxf(fmaxf(fmaxf(redm[0], redm[1]), fmaxf(redm[2], redm[3])),
               fmaxf(fmaxf(redm[4], redm[5]), fmaxf(redm[6], redm[7])));
    float sum = 0.f;
#pragma unroll
    for (int i = 0; i < 16; i++) {
        v[i] = __expf(v[i] - mx);
        sum += v[i];
    }
#pragma unroll
    for (int o = 16; o > 0; o >>= 1)
        sum += __shfl_xor_sync(0xffffffffu, sum, o);
    if ((tid & 31) == 0) reds[tid >> 5] = sum;
    __syncthreads();
    sum = ((reds[0] + reds[1]) + (reds[2] + reds[3]))
        + ((reds[4] + reds[5]) + (reds[6] + reds[7]));
    const float inv = 1.0f / sum;
#pragma unroll
    for (int i = 0; i < 16; i++) {
        const float val = v[i] * inv;
        const size_t idx = row * (size_t)ND + tid + i * 256;
        const __nv_bfloat16 h = __float2bfloat16(val);
        ah[idx] = h;
        al[idx] = __float2bfloat16(val - __bfloat162float(h));
    }
}

// ---------------------------------------------------------------------------
extern "C" void kernel_launch(void* const* d_in, const int* in_sizes, int n_in,
                              void* d_out, int out_size) {
    const float* x  = (const float*)d_in[0];
    const float* Wq = (const float*)d_in[1];
    const float* bq = (const float*)d_in[2];
    const float* Wk = (const float*)d_in[3];
    const float* bk = (const float*)d_in[4];
    const float* Wv = (const float*)d_in[5];
    const float* bv = (const float*)d_in[6];
    float* out = (float*)d_out;

    float *s, *u, *w2, *G, *M1, *PT, *E;
    __nv_bfloat16 *xh, *xl, *wqh, *wql, *wkh, *wkl, *wvh, *wvl;
    __nv_bfloat16 *gh, *gl, *m1h, *m1l, *pth, *ptl, *ah, *al;
    cudaGetSymbolAddress((void**)&s,   g_s);
    cudaGetSymbolAddress((void**)&u,   g_u);
    cudaGetSymbolAddress((void**)&w2,  g_w2);
    cudaGetSymbolAddress((void**)&G,   g_G);
    cudaGetSymbolAddress((void**)&M1,  g_M1);
    cudaGetSymbolAddress((void**)&PT,  g_PT);
    cudaGetSymbolAddress((void**)&E,   g_E);
    cudaGetSymbolAddress((void**)&xh,  g_xh);
    cudaGetSymbolAddress((void**)&xl,  g_xl);
    cudaGetSymbolAddress((void**)&wqh, g_wqh);
    cudaGetSymbolAddress((void**)&wql, g_wql);
    cudaGetSymbolAddress((void**)&wkh, g_wkh);
    cudaGetSymbolAddress((void**)&wkl, g_wkl);
    cudaGetSymbolAddress((void**)&wvh, g_wvh);
    cudaGetSymbolAddress((void**)&wvl, g_wvl);
    cudaGetSymbolAddress((void**)&gh,  g_gh);
    cudaGetSymbolAddress((void**)&gl,  g_gl);
    cudaGetSymbolAddress((void**)&m1h, g_m1h);
    cudaGetSymbolAddress((void**)&m1l, g_m1l);
    cudaGetSymbolAddress((void**)&pth, g_pth);
    cudaGetSymbolAddress((void**)&ptl, g_ptl);
    cudaGetSymbolAddress((void**)&ah,  g_ah);
    cudaGetSymbolAddress((void**)&al,  g_al);

    cudaFuncSetAttribute(mma_nt_gemm<0>, cudaFuncAttributeMaxDynamicSharedMemorySize, MM_SMEM);
    cudaFuncSetAttribute(mma_nt_gemm<1>, cudaFuncAttributeMaxDynamicSharedMemorySize, MM_SMEM);
    cudaFuncSetAttribute(mma_nt_gemm<2>, cudaFuncAttributeMaxDynamicSharedMemorySize, MM_SMEM);

    // 1. s ; u ; w2
    rowsum_k<<<CB * CC, 128>>>(x, s);
    uw_k<<<ND / 128, 128>>>(Wq, Wk, bk, s, u, w2);

    // 2. hi/lo splits of inputs
    split_k<<<(CB * CC * NSP) / 1024, 256>>>(x,  xh,  xl);
    split_k<<<(ND * CC) / 1024, 256>>>(Wq, wqh, wql);
    split_k<<<(ND * CC) / 1024, 256>>>(Wk, wkh, wkl);
    split_k<<<(CC * CC) / 1024, 256>>>(Wv, wvh, wvl);

    // 3. G = X Xᵀ   (M=N=512, K=4096)
    mma_nt_gemm<0><<<dim3(CC / 128, CC / 128, CB), 256, MM_SMEM>>>(
        xh, xl, xh, xl, G, NSP, CC,
        (size_t)CC * NSP, (size_t)CC * NSP, (size_t)CC * CC,
        nullptr, 0, nullptr, 0, nullptr, 0, nullptr, 0);
    split_k<<<(CB * CC * CC) / 1024, 256>>>(G, gh, gl);

    // 4. M1 = Wq Gᵀ (G symmetric)   (M=4096, N=512, K=512)
    mma_nt_gemm<0><<<dim3(CC / 128, ND / 128, CB), 256, MM_SMEM>>>(
        wqh, wql, gh, gl, M1, CC, CC,
        0, (size_t)CC * CC, (size_t)ND * CC,
        nullptr, 0, nullptr, 0, nullptr, 0, nullptr, 0);
    split_k<<<(CB * ND * CC) / 1024, 256>>>(M1, m1h, m1l);

    // 5. E = M1 Wkᵀ + u bkᵀ + bq w2ᵀ   (M=N=4096, K=512)
    mma_nt_gemm<2><<<dim3(ND / 128, ND / 128, CB), 256, MM_SMEM>>>(
        m1h, m1l, wkh, wkl, E, CC, ND,
        (size_t)ND * CC, 0, (size_t)ND * ND,
        u, ND, bk, 0, bq, 0, w2, ND);

    // 6. attn = softmax(E) -> hi/lo bf16
    softmax_bf<<<CB * ND, 256>>>(E, ah, al);

    // 7. PT = attn Xᵀ   (M=4096, N=512, K=4096)
    mma_nt_gemm<0><<<dim3(CC / 128, ND / 128, CB), 256, MM_SMEM>>>(
        ah, al, xh, xl, PT, NSP, CC,
        (size_t)ND * ND, (size_t)CC * NSP, (size_t)ND * CC,
        nullptr, 0, nullptr, 0, nullptr, 0, nullptr, 0);
    split_k<<<(CB * ND * CC) / 1024, 256>>>(PT, pth, ptl);

    // 8. out = Wv PTᵀ + bv   (M=512, N=4096, K=512)
    mma_nt_gemm<1><<<dim3(ND / 128, CC / 128, CB), 256, MM_SMEM>>>(
        wvh, wvl, pth, ptl, out, CC, ND,
        0, (size_t)ND * CC, (size_t)CC * ND,
        bv, 0, nullptr, 0, nullptr, 0, nullptr, 0);

    (void)in_sizes; (void)n_in; (void)out_size;
}

// round 13
// speedup vs baseline: 1.6782x; 1.6782x over previous
#include <cuda_runtime.h>
#include <cuda_bf16.h>
#include <cstddef>
#include <cstdint>

// ---------------------------------------------------------------------------
// HyperNodeAggregation via mma.sync bf16 (compute_103-safe; no tcgen05).
// B=4, C=512, H=W=64, N=HW=4096, node_dim=4096.
//
// All-NT restructure (per batch b; X = x[b] reshaped [C, N], K-major):
//   s   = X·1 ;  u = Wq s ;  w2 = Wk s + N·bk
//   G   = X Xᵀ                                   [C, C]   (symmetric)
//   M1  = Wq Gᵀ(=G)                              [ND, C]
//   E   = M1 Wkᵀ + u bkᵀ + bq w2ᵀ               [ND, ND]
//   A   = softmax_rows(E)
//   PT  = A Xᵀ                                   [ND, C]
//   out = Wv PTᵀ + bv        (Σk A = 1 folds bv)           [C, ND]
//
// Every GEMM is D = A·Bᵀ, both operands K-major -> mma.sync row.col NT.
// fp32 operands split hi/lo bf16; 3 passes (hh+hl+lh), fp32 accumulate.
// R7-R13: cp.async 2-stage pipeline (K-chunks of 32, 80B-pitch conflict-free
// smem), split-K x8 Gram, fused reduce+split, fused hi/lo GEMM epilogues,
// dead fp32 stores dropped (G/M1/PT consumed only as hi/lo bf16).
// ---------------------------------------------------------------------------

#define CB   4
#define CC   512
#define ND   4096
#define NSP  4096
#define GKS  8             // split-K chunks for Gram

// ---------------- scratch (static device memory; no allocs) ----------------
__device__ float g_s  [CB * CC];
__device__ float g_u  [CB * ND];
__device__ float g_w2 [CB * ND];
__device__ float g_Gp [GKS * CB * CC * CC];            // 33.5 MB partials
__device__ float g_E  [(size_t)CB * ND * ND];          // 268 MB

__device__ __nv_bfloat16 g_xh [(size_t)CB * CC * NSP];
__device__ __nv_bfloat16 g_xl [(size_t)CB * CC * NSP];
__device__ __nv_bfloat16 g_wqh[(size_t)ND * CC];
__device__ __nv_bfloat16 g_wql[(size_t)ND * CC];
__device__ __nv_bfloat16 g_wkh[(size_t)ND * CC];
__device__ __nv_bfloat16 g_wkl[(size_t)ND * CC];
__device__ __nv_bfloat16 g_wvh[(size_t)CC * CC];
__device__ __nv_bfloat16 g_wvl[(size_t)CC * CC];
__device__ __nv_bfloat16 g_gh [(size_t)CB * CC * CC];
__device__ __nv_bfloat16 g_gl [(size_t)CB * CC * CC];
__device__ __nv_bfloat16 g_m1h[(size_t)CB * ND * CC];
__device__ __nv_bfloat16 g_m1l[(size_t)CB * ND * CC];
__device__ __nv_bfloat16 g_pth[(size_t)CB * ND * CC];
__device__ __nv_bfloat16 g_ptl[(size_t)CB * ND * CC];
__device__ __nv_bfloat16 g_ah [(size_t)CB * ND * ND];  // 134 MB
__device__ __nv_bfloat16 g_al [(size_t)CB * ND * ND];  // 134 MB

// ---------------- PTX helpers (compute_103-safe only) -----------------------
__device__ __forceinline__ uint32_t smem_u32(const void* p) {
    uint32_t a;
    asm("{ .reg .u64 t; cvta.to.shared.u64 t, %1; cvt.u32.u64 %0, t; }"
        : "=r"(a) : "l"(p));
    return a;
}

__device__ __forceinline__ void cp16(uint32_t dst, const void* src) {
    asm volatile("cp.async.cg.shared.global [%0], [%1], 16;"
                 :: "r"(dst), "l"(__cvta_generic_to_global(src)));
}
#define CP_COMMIT() asm volatile("cp.async.commit_group;" ::: "memory")
#define CP_WAIT(n)  asm volatile("cp.async.wait_group %0;" :: "n"(n) : "memory")

#define LDSM_X4(r, addr)                                                       \
    asm volatile("ldmatrix.sync.aligned.m8n8.x4.shared.b16 {%0,%1,%2,%3}, [%4];" \
                 : "=r"((r)[0]), "=r"((r)[1]), "=r"((r)[2]), "=r"((r)[3])      \
                 : "r"(addr))

#define MMA16816(d, a, b0, b1)                                                 \
    asm volatile("mma.sync.aligned.m16n8k16.row.col.f32.bf16.bf16.f32 "        \
                 "{%0,%1,%2,%3}, {%4,%5,%6,%7}, {%8,%9}, {%0,%1,%2,%3};"       \
                 : "+f"((d)[0]), "+f"((d)[1]), "+f"((d)[2]), "+f"((d)[3])      \
                 : "r"((a)[0]), "r"((a)[1]), "r"((a)[2]), "r"((a)[3]),         \
                   "r"(b0), "r"(b1))

// hi/lo decompose one float pair into two bf16x2 words
__device__ __forceinline__ void hilo2(float x, float y,
                                      __nv_bfloat162& h2, __nv_bfloat162& l2) {
    __nv_bfloat16 hx = __float2bfloat16(x);
    __nv_bfloat16 hy = __float2bfloat16(y);
    h2.x = hx; h2.y = hy;
    l2.x = __float2bfloat16(x - __bfloat162float(hx));
    l2.y = __float2bfloat16(y - __bfloat162float(hy));
}

// ---------------- smem: 2 stages x 4 tiles of 128 rows x 32 bf16 @80B pitch -
// Row pitch 80B: 8 consecutive rows hit offsets {0,80,32,112,64,16,96,48}
// mod 128 -> every ldmatrix.m8n8 octet is bank-conflict-free, no xor needed.
#define TPITCH  80
#define SM_AH   0
#define SM_AL   10240
#define SM_BH   20480
#define SM_BL   30720
#define STAGE   40960
#define MM_SMEM 81920

// ---------------------------------------------------------------------------
// mma_nt_gemm: C[m,n] = sum_k A[m,k]*B[n,k]; A/B hi/lo bf16 K-major
// (lda = ldb = K). Grid: (N/128, M/128, CB*KCH), 256 threads (8 warps).
// blockIdx.z = kc*CB + b; K range = [kc*Kc, kc*Kc+Kc). C += kc*sCk.
// Warp tile 64(M) x 32(N). EPI: 0 none; 1 +em1[m]; 2 +em1*en1 + em2*en2.
// OUTHL=false: store fp32 C.  OUTHL=true: store ONLY hi/lo bf16 (fp32 C is
// dead downstream at those call sites; sCk==0 there).
// ---------------------------------------------------------------------------
template <int EPI, bool OUTHL>
__global__ __launch_bounds__(256, 2)
void mma_nt_gemm(const __nv_bfloat16* __restrict__ Ah, const __nv_bfloat16* __restrict__ Al,
                 const __nv_bfloat16* __restrict__ Bh, const __nv_bfloat16* __restrict__ Bl,
                 float* __restrict__ Cm,
                 __nv_bfloat16* __restrict__ Ch, __nv_bfloat16* __restrict__ Cl,
                 int K, int Kc, int ldc,
                 size_t sA, size_t sB, size_t sC, size_t sCk,
                 const float* __restrict__ em1, int sm1,
                 const float* __restrict__ en1, int sn1,
                 const float* __restrict__ em2, int sm2,
                 const float* __restrict__ en2, int sn2)
{
    extern __shared__ __align__(128) char smem[];
    const uint32_t sb = smem_u32(smem);
    const int tid  = threadIdx.x;
    const int wid  = tid >> 5;
    const int lane = tid & 31;
    const int z    = blockIdx.z;
    const int b    = z % CB;
    const int kc   = z / CB;
    const int n0   = blockIdx.x * 128;
    const int m0   = blockIdx.y * 128;
    const int wm   = wid & 1;        // 2 warps along M
    const int wn   = wid >> 1;       // 4 warps along N

    const __nv_bfloat16* Aph = Ah + (size_t)b * sA + (size_t)m0 * K;
    const __nv_bfloat16* Apl = Al + (size_t)b * sA + (size_t)m0 * K;
    const __nv_bfloat16* Bph = Bh + (size_t)b * sB + (size_t)n0 * K;
    const __nv_bfloat16* Bpl = Bl + (size_t)b * sB + (size_t)n0 * K;
    float* Cp = OUTHL ? nullptr : (Cm + (size_t)b * sC + (size_t)kc * sCk);
    __nv_bfloat16* Chp = OUTHL ? (Ch + (size_t)b * sC) : nullptr;
    __nv_bfloat16* Clp = OUTHL ? (Cl + (size_t)b * sC) : nullptr;

    // ldmatrix lane decomposition
    const int sub = lane >> 3, r8 = lane & 7;
    const int arow  = wm * 64 + (sub & 1) * 8 + r8;   // + mf*16
    const int acsub = sub >> 1;
    const int brow  = wn * 32 + (sub >> 1) * 8 + r8;  // + nf2*16
    const int bcsub = sub & 1;

    float acc[4][4][4];
#pragma unroll
    for (int i = 0; i < 4; i++)
#pragma unroll
        for (int j = 0; j < 4; j++)
#pragma unroll
            for (int k = 0; k < 4; k++) acc[i][j][k] = 0.f;

    const int kBeg = kc * Kc;

    // stage one 32-wide K-chunk (4 tiles) into buffer `buf` via cp.async
    auto stage = [&](int buf, int kb) {
        const uint32_t stg = sb + (uint32_t)buf * STAGE;
        for (int f = tid; f < 512; f += 256) {
            const int row = f >> 2, c = f & 3;
            const uint32_t off = (uint32_t)(row * TPITCH + c * 16);
            const size_t g = (size_t)row * K + kb + c * 8;
            cp16(stg + SM_AH + off, Aph + g);
            cp16(stg + SM_AL + off, Apl + g);
            cp16(stg + SM_BH + off, Bph + g);
            cp16(stg + SM_BL + off, Bpl + g);
        }
        CP_COMMIT();
    };

    const int nch = Kc >> 5;
    stage(0, kBeg);

    for (int ch = 0; ch < nch; ch++) {
        if (ch + 1 < nch) {
            stage((ch + 1) & 1, kBeg + (ch + 1) * 32);
            CP_WAIT(1);
        } else {
            CP_WAIT(0);
        }
        __syncthreads();

        const uint32_t base = sb + (uint32_t)(ch & 1) * STAGE;
#pragma unroll
        for (int pass = 0; pass < 3; pass++) {      // hh, hl, lh
            const uint32_t abase = base + ((pass == 2) ? SM_AL : SM_AH);
            const uint32_t bbase = base + ((pass == 1) ? SM_BL : SM_BH);
#pragma unroll
            for (int ks = 0; ks < 2; ks++) {        // 2 x k16 within the 32-chunk
                uint32_t aR[4][4];
#pragma unroll
                for (int mf = 0; mf < 4; mf++) {
                    const int row = arow + mf * 16;
                    const uint32_t ad = abase + (uint32_t)(row * TPITCH)
                                      + (uint32_t)((2 * ks + acsub) << 4);
                    LDSM_X4(aR[mf], ad);
                }
                uint32_t bR[2][4];
#pragma unroll
                for (int nf2 = 0; nf2 < 2; nf2++) {
                    const int row = brow + nf2 * 16;
                    const uint32_t bd = bbase + (uint32_t)(row * TPITCH)
                                      + (uint32_t)((2 * ks + bcsub) << 4);
                    LDSM_X4(bR[nf2], bd);
                }
#pragma unroll
                for (int mf = 0; mf < 4; mf++)
#pragma unroll
                    for (int nf = 0; nf < 4; nf++)
                        MMA16816(acc[mf][nf], aR[mf],
                                 bR[nf >> 1][(nf & 1) * 2 + 0],
                                 bR[nf >> 1][(nf & 1) * 2 + 1]);
            }
        }
        __syncthreads();
    }

    // ---- epilogue: c0,c1 at (m=g, n=2t..2t+1); c2,c3 at (m=g+8, same n)
    const int g = lane >> 2, t = lane & 3;
#pragma unroll
    for (int mf = 0; mf < 4; mf++) {
        const int mA = m0 + wm * 64 + mf * 16 + g;
        const int mB = mA + 8;
        float e1A = 0.f, e2A = 0.f, e1B = 0.f, e2B = 0.f;
        if (EPI == 1) {
            e1A = __ldg(em1 + (size_t)b * sm1 + mA);
            e1B = __ldg(em1 + (size_t)b * sm1 + mB);
        }
        if (EPI == 2) {
            e1A = __ldg(em1 + (size_t)b * sm1 + mA);
            e2A = __ldg(em2 + (size_t)b * sm2 + mA);
            e1B = __ldg(em1 + (size_t)b * sm1 + mB);
            e2B = __ldg(em2 + (size_t)b * sm2 + mB);
        }
#pragma unroll
        for (int nf = 0; nf < 4; nf++) {
            const int n = n0 + wn * 32 + nf * 8 + t * 2;
            float2 vA, vB;
            vA.x = acc[mf][nf][0]; vA.y = acc[mf][nf][1];
            vB.x = acc[mf][nf][2]; vB.y = acc[mf][nf][3];
            if (EPI == 1) { vA.x += e1A; vA.y += e1A; vB.x += e1B; vB.y += e1B; }
            if (EPI == 2) {
                const float n1a = __ldg(en1 + (size_t)b * sn1 + n);
                const float n1b = __ldg(en1 + (size_t)b * sn1 + n + 1);
                const float n2a = __ldg(en2 + (size_t)b * sn2 + n);
                const float n2b = __ldg(en2 + (size_t)b * sn2 + n + 1);
                vA.x += e1A * n1a + e2A * n2a;  vA.y += e1A * n1b + e2A * n2b;
                vB.x += e1B * n1a + e2B * n2a;  vB.y += e1B * n1b + e2B * n2b;
            }
            if (OUTHL) {
                __nv_bfloat162 h2, l2;
                hilo2(vA.x, vA.y, h2, l2);
                *(__nv_bfloat162*)(Chp + (size_t)mA * ldc + n) = h2;
                *(__nv_bfloat162*)(Clp + (size_t)mA * ldc + n) = l2;
                hilo2(vB.x, vB.y, h2, l2);
                *(__nv_bfloat162*)(Chp + (size_t)mB * ldc + n) = h2;
                *(__nv_bfloat162*)(Clp + (size_t)mB * ldc + n) = l2;
            } else {
                *(float2*)(Cp + (size_t)mA * ldc + n) = vA;
                *(float2*)(Cp + (size_t)mB * ldc + n) = vB;
            }
        }
    }
}

// ---------------------------------------------------------------------------
// Deterministic split-K reduction for Gram partials -> hi/lo bf16 only
// ---------------------------------------------------------------------------
__global__ __launch_bounds__(256) void reduce_g(const float* __restrict__ part,
                                                __nv_bfloat16* __restrict__ gh,
                                                __nv_bfloat16* __restrict__ gl,
                                                int n, int chunks, size_t cs) {
    int i = blockIdx.x * 256 + threadIdx.x;
    if (i < n) {
        float a = 0.f;
        for (int c = 0; c < chunks; c++) a += part[(size_t)c * cs + i];
        const __nv_bfloat16 h = __float2bfloat16(a);
        gh[i] = h;
        gl[i] = __float2bfloat16(a - __bfloat162float(h));
    }
}

// ---------------------------------------------------------------------------
// hi/lo split: h = bf16(x), l = bf16(x - h). 4 floats/thread.
// ---------------------------------------------------------------------------
__global__ __launch_bounds__(256) void split_k(const float* __restrict__ src,
                                               __nv_bfloat16* __restrict__ h,
                                               __nv_bfloat16* __restrict__ l) {
    const size_t i = (size_t)blockIdx.x * 256 + threadIdx.x;
    const float4 v = ((const float4*)src)[i];
    __nv_bfloat162 h01, h23, l01, l23;
    hilo2(v.x, v.y, h01, l01);
    hilo2(v.z, v.w, h23, l23);
    ((__nv_bfloat162*)h)[2 * i + 0] = h01;
    ((__nv_bfloat162*)h)[2 * i + 1] = h23;
    ((__nv_bfloat162*)l)[2 * i + 0] = l01;
    ((__nv_bfloat162*)l)[2 * i + 1] = l23;
}

// ---------------------------------------------------------------------------
__global__ __launch_bounds__(128) void rowsum_k(const float* __restrict__ x,
                                                float* __restrict__ s) {
    const int rc = blockIdx.x;
    const float4* p4 = (const float4*)(x + (size_t)rc * NSP);
    const int tid = threadIdx.x;
    float a = 0.f;
    for (int i = tid; i < NSP / 4; i += 128) {
        float4 v = p4[i];
        a += (v.x + v.y) + (v.z + v.w);
    }
#pragma unroll
    for (int o = 16; o > 0; o >>= 1) a += __shfl_xor_sync(0xffffffffu, a, o);
    __shared__ float red[4];
    if ((tid & 31) == 0) red[tid >> 5] = a;
    __syncthreads();
    if (tid == 0) s[rc] = (red[0] + red[1]) + (red[2] + red[3]);
}

// ---------------------------------------------------------------------------
__global__ __launch_bounds__(128) void uw_k(const float* __restrict__ Wq,
                                            const float* __restrict__ Wk,
                                            const float* __restrict__ bk,
                                            const float* __restrict__ s,
                                            float* __restrict__ u,
                                            float* __restrict__ w2) {
    __shared__ float ss[CB * CC];
    const int tid = threadIdx.x;
    for (int i = tid; i < CB * CC; i += 128) ss[i] = s[i];
    __syncthreads();
    const int q = blockIdx.x * 128 + tid;
    float au[CB] = {0.f, 0.f, 0.f, 0.f};
    float aw[CB] = {0.f, 0.f, 0.f, 0.f};
    const float* wqr = Wq + (size_t)q * CC;
    const float* wkr = Wk + (size_t)q * CC;
    for (int c = 0; c < CC; c++) {
        const float wq = wqr[c], wk = wkr[c];
#pragma unroll
        for (int bb = 0; bb < CB; bb++) {
            const float sv = ss[bb * CC + c];
            au[bb] += wq * sv;
            aw[bb] += wk * sv;
        }
    }
    const float bkv = bk[q];
#pragma unroll
    for (int bb = 0; bb < CB; bb++) {
        u[bb * ND + q]  = au[bb];
        w2[bb * ND + q] = aw[bb] + (float)NSP * bkv;
    }
}

// ---------------------------------------------------------------------------
// Row softmax over E (fp32), writing attn directly as hi/lo bf16.
// ---------------------------------------------------------------------------
__global__ __launch_bounds__(256) void softmax_bf(const float* __restrict__ E,
                                                  __nv_bfloat16* __restrict__ ah,
                                                  __nv_bfloat16* __restrict__ al) {
    const size_t row = blockIdx.x;
    const float* p = E + row * (size_t)ND;
    const int tid = threadIdx.x;
    float v[16];
    float mx = -3.4e38f;
#pragma unroll
    for (int i = 0; i < 16; i++) {
        v[i] = p[tid + i * 256];
        mx = fmaxf(mx, v[i]);
    }
#pragma unroll
    for (int o = 16; o > 0; o >>= 1)
        mx = fmaxf(mx, __shfl_xor_sync(0xffffffffu, mx, o));
    __shared__ float redm[8];
    __shared__ float reds[8];
    if ((tid & 31) == 0) redm[tid >> 5] = mx;
    __syncthreads();
    mx = fmaxf(fmaxf(fmaxf(redm[0], redm[1]), fmaxf(redm[2], redm[3])),
               fmaxf(fmaxf(redm[4], redm[5]), fmaxf(redm[6], redm[7])));
    float sum = 0.f;
#pragma unroll
    for (int i = 0; i < 16; i++) {
        v[i] = __expf(v[i] - mx);
        sum += v[i];
    }
#pragma unroll
    for (int o = 16; o > 0; o >>= 1)
        sum += __shfl_xor_sync(0xffffffffu, sum, o);
    if ((tid & 31) == 0) reds[tid >> 5] = sum;
    __syncthreads();
    sum = ((reds[0] + reds[1]) + (reds[2] + reds[3]))
        + ((reds[4] + reds[5]) + (reds[6] + reds[7]));
    const float inv = 1.0f / sum;
#pragma unroll
    for (int i = 0; i < 16; i++) {
        const float val = v[i] * inv;
        const size_t idx = row * (size_t)ND + tid + i * 256;
        const __nv_bfloat16 h = __float2bfloat16(val);
        ah[idx] = h;
        al[idx] = __float2bfloat16(val - __bfloat162float(h));
    }
}

// ---------------------------------------------------------------------------
extern "C" void kernel_launch(void* const* d_in, const int* in_sizes, int n_in,
                              void* d_out, int out_size) {
    const float* x  = (const float*)d_in[0];
    const float* Wq = (const float*)d_in[1];
    const float* bq = (const float*)d_in[2];
    const float* Wk = (const float*)d_in[3];
    const float* bk = (const float*)d_in[4];
    const float* Wv = (const float*)d_in[5];
    const float* bv = (const float*)d_in[6];
    float* out = (float*)d_out;

    float *s, *u, *w2, *Gp, *E;
    __nv_bfloat16 *xh, *xl, *wqh, *wql, *wkh, *wkl, *wvh, *wvl;
    __nv_bfloat16 *gh, *gl, *m1h, *m1l, *pth, *ptl, *ah, *al;
    cudaGetSymbolAddress((void**)&s,   g_s);
    cudaGetSymbolAddress((void**)&u,   g_u);
    cudaGetSymbolAddress((void**)&w2,  g_w2);
    cudaGetSymbolAddress((void**)&Gp,  g_Gp);
    cudaGetSymbolAddress((void**)&E,   g_E);
    cudaGetSymbolAddress((void**)&xh,  g_xh);
    cudaGetSymbolAddress((void**)&xl,  g_xl);
    cudaGetSymbolAddress((void**)&wqh, g_wqh);
    cudaGetSymbolAddress((void**)&wql, g_wql);
    cudaGetSymbolAddress((void**)&wkh, g_wkh);
    cudaGetSymbolAddress((void**)&wkl, g_wkl);
    cudaGetSymbolAddress((void**)&wvh, g_wvh);
    cudaGetSymbolAddress((void**)&wvl, g_wvl);
    cudaGetSymbolAddress((void**)&gh,  g_gh);
    cudaGetSymbolAddress((void**)&gl,  g_gl);
    cudaGetSymbolAddress((void**)&m1h, g_m1h);
    cudaGetSymbolAddress((void**)&m1l, g_m1l);
    cudaGetSymbolAddress((void**)&pth, g_pth);
    cudaGetSymbolAddress((void**)&ptl, g_ptl);
    cudaGetSymbolAddress((void**)&ah,  g_ah);
    cudaGetSymbolAddress((void**)&al,  g_al);

    cudaFuncSetAttribute((const void*)mma_nt_gemm<0, false>, cudaFuncAttributeMaxDynamicSharedMemorySize, MM_SMEM);
    cudaFuncSetAttribute((const void*)mma_nt_gemm<0, true>,  cudaFuncAttributeMaxDynamicSharedMemorySize, MM_SMEM);
    cudaFuncSetAttribute((const void*)mma_nt_gemm<1, false>, cudaFuncAttributeMaxDynamicSharedMemorySize, MM_SMEM);
    cudaFuncSetAttribute((const void*)mma_nt_gemm<2, false>, cudaFuncAttributeMaxDynamicSharedMemorySize, MM_SMEM);

    // 1. s ; u ; w2
    rowsum_k<<<CB * CC, 128>>>(x, s);
    uw_k<<<ND / 128, 128>>>(Wq, Wk, bk, s, u, w2);

    // 2. hi/lo splits of inputs
    split_k<<<(CB * CC * NSP) / 1024, 256>>>(x,  xh,  xl);
    split_k<<<(ND * CC) / 1024, 256>>>(Wq, wqh, wql);
    split_k<<<(ND * CC) / 1024, 256>>>(Wk, wkh, wkl);
    split_k<<<(CC * CC) / 1024, 256>>>(Wv, wvh, wvl);

    // 3. G = X Xᵀ   (M=N=512, K=4096 split-K x8 -> 512 CTAs), fused reduce+split
    mma_nt_gemm<0, false><<<dim3(CC / 128, CC / 128, CB * GKS), 256, MM_SMEM>>>(
        xh, xl, xh, xl, Gp, nullptr, nullptr, NSP, NSP / GKS, CC,
        (size_t)CC * NSP, (size_t)CC * NSP, (size_t)CC * CC, (size_t)CB * CC * CC,
        nullptr, 0, nullptr, 0, nullptr, 0, nullptr, 0);
    reduce_g<<<(CB * CC * CC + 255) / 256, 256>>>(
        Gp, gh, gl, CB * CC * CC, GKS, (size_t)CB * CC * CC);

    // 4. M1 = Wq Gᵀ (G symmetric)   (M=4096, N=512, K=512); hi/lo-only out
    mma_nt_gemm<0, true><<<dim3(CC / 128, ND / 128, CB), 256, MM_SMEM>>>(
        wqh, wql, gh, gl, nullptr, m1h, m1l, CC, CC, CC,
        0, (size_t)CC * CC, (size_t)ND * CC, 0,
        nullptr, 0, nullptr, 0, nullptr, 0, nullptr, 0);

    // 5. E = M1 Wkᵀ + u bkᵀ + bq w2ᵀ   (M=N=4096, K=512)
    mma_nt_gemm<2, false><<<dim3(ND / 128, ND / 128, CB), 256, MM_SMEM>>>(
        m1h, m1l, wkh, wkl, E, nullptr, nullptr, CC, CC, ND,
        (size_t)ND * CC, 0, (size_t)ND * ND, 0,
        u, ND, bk, 0, bq, 0, w2, ND);

    // 6. attn = softmax(E) -> hi/lo bf16
    softmax_bf<<<CB * ND, 256>>>(E, ah, al);

    // 7. PT = attn Xᵀ   (M=4096, N=512, K=4096); hi/lo-only out
    mma_nt_gemm<0, true><<<dim3(CC / 128, ND / 128, CB), 256, MM_SMEM>>>(
        ah, al, xh, xl, nullptr, pth, ptl, NSP, NSP, CC,
        (size_t)ND * ND, (size_t)CC * NSP, (size_t)ND * CC, 0,
        nullptr, 0, nullptr, 0, nullptr, 0, nullptr, 0);

    // 8. out = Wv PTᵀ + bv   (M=512, N=4096, K=512)
    mma_nt_gemm<1, false><<<dim3(ND / 128, CC / 128, CB), 256, MM_SMEM>>>(
        wvh, wvl, pth, ptl, out, nullptr, nullptr, CC, CC, ND,
        0, (size_t)ND * CC, (size_t)CC * ND, 0,
        bv, 0, nullptr, 0, nullptr, 0, nullptr, 0);

    (void)in_sizes; (void)n_in; (void)out_size;
}